// round 7
// baseline (speedup 1.0000x reference)
#include <cuda_runtime.h>

#define BATCH 4
#define NQ    2048
#define NK    2048
#define DQ    1024
#define NH    8
#define HD    64
#define INNER 512
#define KKEEP 64

// Scratch (device globals; allocation-free contract)
__device__ float g_Q [BATCH * NQ * INNER];          // 16.8 MB
__device__ float g_KV[BATCH * NK * 2 * INNER];      // 33.5 MB  (K: cols 0..511, V: 512..1023)
__device__ float g_S [134217728];                   // 512 MB   sim [B*H][NQ][NK]
__device__ float g_O [BATCH * NQ * INNER];          // 16.8 MB

// ---- tf32 split helpers + warp MMA --------------------------------------------
__device__ __forceinline__ void split_tf32(float v, unsigned& hi, unsigned& lo) {
    asm("cvt.rna.tf32.f32 %0, %1;" : "=r"(hi) : "f"(v));
    float l = v - __uint_as_float(hi);
    asm("cvt.rna.tf32.f32 %0, %1;" : "=r"(lo) : "f"(l));
}

#define MMA_TF32(c, a, b0, b1) \
    asm("mma.sync.aligned.m16n8k8.row.col.f32.tf32.tf32.f32 " \
        "{%0,%1,%2,%3}, {%4,%5,%6,%7}, {%8,%9}, {%0,%1,%2,%3};" \
        : "+f"((c)[0]), "+f"((c)[1]), "+f"((c)[2]), "+f"((c)[3]) \
        : "r"((a)[0]), "r"((a)[1]), "r"((a)[2]), "r"((a)[3]), "r"(b0), "r"(b1))

// ---------------------------------------------------------------------------
// fp32 SGEMM (NN), double-buffered (Q and KV projections; precision-critical).
// ---------------------------------------------------------------------------
__global__ void __launch_bounds__(256) sgemm_nn(
    const float* __restrict__ A, const float* __restrict__ Bm,
    float* __restrict__ C, int M, int N, int K)
{
    __shared__ float As[2][8][128];
    __shared__ float Bs[2][8][128];
    const int tid  = threadIdx.x;
    const int row0 = blockIdx.y * 128, col0 = blockIdx.x * 128;
    const int tx   = tid & 15, ty = tid >> 4;
    const int a_row = tid >> 1, a_k = (tid & 1) * 4;
    const int b_k   = tid >> 5, b_col = (tid & 31) * 4;
    const float* Ap = A  + (size_t)(row0 + a_row) * K + a_k;
    const float* Bp = Bm + (size_t)b_k * N + col0 + b_col;

    float acc[8][8];
#pragma unroll
    for (int i = 0; i < 8; i++)
#pragma unroll
        for (int j = 0; j < 8; j++) acc[i][j] = 0.f;

    {
        float4 av = *(const float4*)Ap;
        float4 bv = *(const float4*)Bp;
        As[0][a_k + 0][a_row] = av.x;
        As[0][a_k + 1][a_row] = av.y;
        As[0][a_k + 2][a_row] = av.z;
        As[0][a_k + 3][a_row] = av.w;
        *(float4*)&Bs[0][b_k][b_col] = bv;
    }
    __syncthreads();

    int buf = 0;
    for (int k0 = 8; k0 <= K; k0 += 8) {
        const bool has = (k0 < K);
        float4 av, bv;
        if (has) {
            av = *(const float4*)(Ap + k0);
            bv = *(const float4*)(Bp + (size_t)k0 * N);
        }
#pragma unroll
        for (int kk = 0; kk < 8; kk++) {
            float af[8], bf[8];
            *(float4*)&af[0] = *(const float4*)&As[buf][kk][ty * 4];
            *(float4*)&af[4] = *(const float4*)&As[buf][kk][ty * 4 + 64];
            *(float4*)&bf[0] = *(const float4*)&Bs[buf][kk][tx * 4];
            *(float4*)&bf[4] = *(const float4*)&Bs[buf][kk][tx * 4 + 64];
#pragma unroll
            for (int i = 0; i < 8; i++)
#pragma unroll
                for (int j = 0; j < 8; j++)
                    acc[i][j] += af[i] * bf[j];
        }
        if (has) {
            const int nb = buf ^ 1;
            As[nb][a_k + 0][a_row] = av.x;
            As[nb][a_k + 1][a_row] = av.y;
            As[nb][a_k + 2][a_row] = av.z;
            As[nb][a_k + 3][a_row] = av.w;
            *(float4*)&Bs[nb][b_k][b_col] = bv;
            __syncthreads();
            buf = nb;
        }
    }

#pragma unroll
    for (int ih = 0; ih < 2; ih++)
#pragma unroll
        for (int ii = 0; ii < 4; ii++) {
            int row = row0 + ty * 4 + ih * 64 + ii;
            float* Cp = C + (size_t)row * N + col0;
#pragma unroll
            for (int jh = 0; jh < 2; jh++) {
                int c = tx * 4 + jh * 64;
                float4 v;
                v.x = acc[ih * 4 + ii][jh * 4 + 0];
                v.y = acc[ih * 4 + ii][jh * 4 + 1];
                v.z = acc[ih * 4 + ii][jh * 4 + 2];
                v.w = acc[ih * 4 + ii][jh * 4 + 3];
                *(float4*)(Cp + c) = v;
            }
        }
}

// ---------------------------------------------------------------------------
// sim via 4-term TF32 tensor-core MMA (NT): S = 0.125 * Q_h . K_h^T
// Block = 128x128 S tile; 8 warps, warp tile 32x64, m16n8k8, K=64.
// ---------------------------------------------------------------------------
__global__ void __launch_bounds__(256) sim_tf32(
    const float* __restrict__ Q, const float* __restrict__ KV, float* __restrict__ S)
{
    extern __shared__ float sm[];
    float* Qs = sm;              // [128][68]
    float* Ks = sm + 128 * 68;   // [128][68]
    const int bh = blockIdx.z, b = bh >> 3, h = bh & 7;
    const int i0 = blockIdx.y * 128, j0 = blockIdx.x * 128;
    const int tid = threadIdx.x;

#pragma unroll
    for (int l = 0; l < 8; l++) {
        int idx = tid + l * 256;
        int row = idx >> 4, k0 = (idx & 15) * 4;
        float4 q4 = *(const float4*)(Q  + (size_t)(b * NQ + i0 + row) * INNER       + h * HD + k0);
        *(float4*)(Qs + row * 68 + k0) = q4;
        float4 k4 = *(const float4*)(KV + (size_t)(b * NK + j0 + row) * (2 * INNER) + h * HD + k0);
        *(float4*)(Ks + row * 68 + k0) = k4;
    }
    __syncthreads();

    const int lane = tid & 31, wid = tid >> 5;
    const int wm = (wid & 3) * 32, wn = (wid >> 2) * 64;
    const int gr = lane >> 2, gc = lane & 3;

    float acc[2][8][4];
#pragma unroll
    for (int mi = 0; mi < 2; mi++)
#pragma unroll
        for (int ni = 0; ni < 8; ni++)
#pragma unroll
            for (int q = 0; q < 4; q++) acc[mi][ni][q] = 0.f;

#pragma unroll
    for (int k0 = 0; k0 < 64; k0 += 8) {
        unsigned ahi[2][4], alo[2][4];
#pragma unroll
        for (int mi = 0; mi < 2; mi++) {
            int m = wm + mi * 16 + gr;
            split_tf32(Qs[m * 68 + k0 + gc],           ahi[mi][0], alo[mi][0]);
            split_tf32(Qs[(m + 8) * 68 + k0 + gc],     ahi[mi][1], alo[mi][1]);
            split_tf32(Qs[m * 68 + k0 + 4 + gc],       ahi[mi][2], alo[mi][2]);
            split_tf32(Qs[(m + 8) * 68 + k0 + 4 + gc], ahi[mi][3], alo[mi][3]);
        }
#pragma unroll
        for (int ni = 0; ni < 8; ni++) {
            int n = wn + ni * 8 + gr;
            unsigned bh0, bl0, bh1, bl1;
            split_tf32(Ks[n * 68 + k0 + gc],     bh0, bl0);
            split_tf32(Ks[n * 68 + k0 + 4 + gc], bh1, bl1);
#pragma unroll
            for (int mi = 0; mi < 2; mi++) {
                MMA_TF32(acc[mi][ni], alo[mi], bl0, bl1);  // lo*lo (4th term)
                MMA_TF32(acc[mi][ni], ahi[mi], bl0, bl1);
                MMA_TF32(acc[mi][ni], alo[mi], bh0, bh1);
                MMA_TF32(acc[mi][ni], ahi[mi], bh0, bh1);
            }
        }
    }

    const float scale = 0.125f;
#pragma unroll
    for (int mi = 0; mi < 2; mi++)
#pragma unroll
        for (int ni = 0; ni < 8; ni++) {
            int row = i0 + wm + mi * 16 + gr;
            int col = j0 + wn + ni * 8 + gc * 2;
            float2 v0 = { acc[mi][ni][0] * scale, acc[mi][ni][1] * scale };
            __stcs((float2*)(S + ((size_t)bh * NQ + row) * NK + col), v0);
            float2 v1 = { acc[mi][ni][2] * scale, acc[mi][ni][3] * scale };
            __stcs((float2*)(S + ((size_t)bh * NQ + row + 8) * NK + col), v1);
        }
}

// ---------------------------------------------------------------------------
// out-projection via 3xTF32 MMA (NN): C = O @ Wout + bias  (post-selection; safe)
// ---------------------------------------------------------------------------
__global__ void __launch_bounds__(256) out_tf32(
    const float* __restrict__ A, const float* __restrict__ Bm,
    const float* __restrict__ bias, float* __restrict__ C)
{
    __shared__ float As[2][128 * 12];
    __shared__ float Bs[2][128 * 12];
    const int tid  = threadIdx.x;
    const int row0 = blockIdx.y * 128, col0 = blockIdx.x * 128;
    const int a_row = tid >> 1, a_k = (tid & 1) * 4;
    const int b_k   = tid >> 5, b_n = (tid & 31) * 4;
    const float* Ap = A  + (size_t)(row0 + a_row) * INNER + a_k;
    const float* Bp = Bm + (size_t)b_k * DQ + col0 + b_n;

    {
        float4 a4 = *(const float4*)Ap;
        *(float4*)(As[0] + a_row * 12 + a_k) = a4;
        float4 b4 = *(const float4*)Bp;
        Bs[0][(b_n + 0) * 12 + b_k] = b4.x;
        Bs[0][(b_n + 1) * 12 + b_k] = b4.y;
        Bs[0][(b_n + 2) * 12 + b_k] = b4.z;
        Bs[0][(b_n + 3) * 12 + b_k] = b4.w;
    }
    __syncthreads();

    const int lane = tid & 31, wid = tid >> 5;
    const int wm = (wid & 3) * 32, wn = (wid >> 2) * 64;
    const int gr = lane >> 2, gc = lane & 3;

    float acc[2][8][4];
#pragma unroll
    for (int mi = 0; mi < 2; mi++)
#pragma unroll
        for (int ni = 0; ni < 8; ni++)
#pragma unroll
            for (int q = 0; q < 4; q++) acc[mi][ni][q] = 0.f;

    int buf = 0;
    for (int k0 = 8; k0 <= INNER; k0 += 8) {
        const bool has = (k0 < INNER);
        float4 a4, b4;
        if (has) {
            a4 = *(const float4*)(Ap + k0);
            b4 = *(const float4*)(Bp + (size_t)k0 * DQ);
        }
        unsigned ahi[2][4], alo[2][4];
#pragma unroll
        for (int mi = 0; mi < 2; mi++) {
            int m = wm + mi * 16 + gr;
            split_tf32(As[buf][m * 12 + gc],           ahi[mi][0], alo[mi][0]);
            split_tf32(As[buf][(m + 8) * 12 + gc],     ahi[mi][1], alo[mi][1]);
            split_tf32(As[buf][m * 12 + 4 + gc],       ahi[mi][2], alo[mi][2]);
            split_tf32(As[buf][(m + 8) * 12 + 4 + gc], ahi[mi][3], alo[mi][3]);
        }
#pragma unroll
        for (int ni = 0; ni < 8; ni++) {
            int n = wn + ni * 8 + gr;
            unsigned bh0, bl0, bh1, bl1;
            split_tf32(Bs[buf][n * 12 + gc],     bh0, bl0);
            split_tf32(Bs[buf][n * 12 + 4 + gc], bh1, bl1);
#pragma unroll
            for (int mi = 0; mi < 2; mi++) {
                MMA_TF32(acc[mi][ni], ahi[mi], bh0, bh1);
                MMA_TF32(acc[mi][ni], ahi[mi], bl0, bl1);
                MMA_TF32(acc[mi][ni], alo[mi], bh0, bh1);
            }
        }
        if (has) {
            const int nb = buf ^ 1;
            *(float4*)(As[nb] + a_row * 12 + a_k) = a4;
            Bs[nb][(b_n + 0) * 12 + b_k] = b4.x;
            Bs[nb][(b_n + 1) * 12 + b_k] = b4.y;
            Bs[nb][(b_n + 2) * 12 + b_k] = b4.z;
            Bs[nb][(b_n + 3) * 12 + b_k] = b4.w;
            __syncthreads();
            buf = nb;
        }
    }

#pragma unroll
    for (int mi = 0; mi < 2; mi++)
#pragma unroll
        for (int ni = 0; ni < 8; ni++) {
            int row = row0 + wm + mi * 16 + gr;
            int col = col0 + wn + ni * 8 + gc * 2;
            float bx = bias[col], by = bias[col + 1];
            float2 v0 = { acc[mi][ni][0] + bx, acc[mi][ni][1] + by };
            *(float2*)(C + (size_t)row * DQ + col) = v0;
            float2 v1 = { acc[mi][ni][2] + bx, acc[mi][ni][3] + by };
            *(float2*)(C + (size_t)(row + 8) * DQ + col) = v1;
        }
}

// ---------------------------------------------------------------------------
// Per query row: exact top-64 via rank-based prefilter (no histogram).
//  t_hat = 64th-largest per-thread max  =>  all true top-64 >= t_hat (proof:
//  >=64 threads have max >= t_hat => >=64 values >= t_hat => 64th value >= t_hat).
//  Compact candidates (E ~87), exact rank-select on composite keys
//  (value desc, index asc  == jax.lax.top_k tie semantics), softmax, sparse PV.
// ---------------------------------------------------------------------------
__device__ __forceinline__ unsigned fkey(float f) {
    unsigned u = __float_as_uint(f);
    return (u & 0x80000000u) ? ~u : (u | 0x80000000u);
}
__device__ __forceinline__ float unfkey(unsigned k) {
    unsigned u = (k & 0x80000000u) ? (k & 0x7fffffffu) : ~k;
    return __uint_as_float(u);
}

__global__ void __launch_bounds__(128, 12) topk_attn(
    const float* __restrict__ S, const float* __restrict__ KV, float* __restrict__ O)
{
    const int r  = blockIdx.x;
    const int bh = r >> 11, i = r & 2047;
    const int b  = bh >> 3, h = bh & 7;
    const float* srow = S + (size_t)r * NK;

    __shared__ unsigned long long ckey[2048];   // worst-case candidate buffer
    __shared__ float maxa[128];
    __shared__ float selv[64];
    __shared__ int   seli[64];
    __shared__ float s_thr, s_wsum;
    __shared__ int   s_ncand;
    __shared__ float w[64];
    __shared__ float part[64];

    const int tid = threadIdx.x;
    if (tid == 0) s_ncand = 0;

    float vals[16];
#pragma unroll
    for (int t = 0; t < 4; t++) {
        float4 v = __ldcs((const float4*)srow + tid + t * 128);
        vals[t * 4 + 0] = v.x; vals[t * 4 + 1] = v.y;
        vals[t * 4 + 2] = v.z; vals[t * 4 + 3] = v.w;
    }
    float tmax = vals[0];
#pragma unroll
    for (int t = 1; t < 16; t++) tmax = fmaxf(tmax, vals[t]);
    maxa[tid] = tmax;
    __syncthreads();

    // rank of own max among 128 maxima (desc, tie -> lower tid). Unique ranks.
    {
        int rank = 0;
        for (int o = 0; o < 128; o++) {
            float mo = maxa[o];
            rank += (mo > tmax) || (mo == tmax && o < tid);
        }
        if (rank == KKEEP - 1) s_thr = tmax;
    }
    __syncthreads();
    const float thr = s_thr;

    // warp-aggregated compaction of candidates (v >= thr)
    const int lane = tid & 31;
#pragma unroll
    for (int t = 0; t < 16; t++) {
        bool p = (vals[t] >= thr);
        unsigned ball = __ballot_sync(0xffffffffu, p);
        if (ball) {
            int base;
            if (lane == 0) base = atomicAdd(&s_ncand, __popc(ball));
            base = __shfl_sync(0xffffffffu, base, 0);
            if (p) {
                int off = __popc(ball & ((1u << lane) - 1u));
                int j = (tid + (t >> 2) * 128) * 4 + (t & 3);
                ckey[base + off] =
                    ((unsigned long long)fkey(vals[t]) << 32) | (unsigned)(2047 - j);
            }
        }
    }
    __syncthreads();

    // exact top-64 by rank over candidates; write directly at final position
    const int nc = s_ncand;
    for (int c = tid; c < nc; c += 128) {
        unsigned long long k = ckey[c];
        int rk = 0;
        for (int o = 0; o < nc; o++) rk += (ckey[o] > k);
        if (rk < KKEEP) {
            selv[rk] = unfkey((unsigned)(k >> 32));
            seli[rk] = 2047 - (int)(k & 0xffffffffu);
        }
    }
    __syncthreads();   // selv[0] = row max

    if (tid < 64) w[tid] = expf(selv[tid] - selv[0]);
    __syncthreads();
    if (tid < 32) {
        float s = w[tid] + w[tid + 32];
#pragma unroll
        for (int off = 16; off; off >>= 1)
            s += __shfl_xor_sync(0xffffffffu, s, off);
        if (tid == 0) s_wsum = s;
    }
    __syncthreads();

    const int g = tid >> 6, d = tid & 63;
    const float* Vbase = KV + (size_t)b * NK * (2 * INNER) + INNER + h * HD + d;
    float acc = 0.f;
#pragma unroll 4
    for (int jj = 0; jj < 32; jj++) {
        int j = g * 32 + jj;
        acc += w[j] * Vbase[(size_t)seli[j] * (2 * INNER)];
    }
    if (g == 1) part[d] = acc;
    __syncthreads();
    if (g == 0) {
        float o = (acc + part[d]) / s_wsum;
        O[((size_t)(b * NQ + i)) * INNER + h * HD + d] = o;
    }
}

// ---------------------------------------------------------------------------
extern "C" void kernel_launch(void* const* d_in, const int* in_sizes, int n_in,
                              void* d_out, int out_size)
{
    const float* x    = (const float*)d_in[0];
    const float* ctx  = (const float*)d_in[1];
    const float* Wq   = (const float*)d_in[2];
    const float* Wkv  = (const float*)d_in[3];
    const float* Wout = (const float*)d_in[4];
    const float* bout = (const float*)d_in[5];
    float* out = (float*)d_out;

    float *pQ, *pKV, *pS, *pO;
    cudaGetSymbolAddress((void**)&pQ,  g_Q);
    cudaGetSymbolAddress((void**)&pKV, g_KV);
    cudaGetSymbolAddress((void**)&pS,  g_S);
    cudaGetSymbolAddress((void**)&pO,  g_O);

    const int simSmem = 2 * 128 * 68 * sizeof(float);   // 69632 B
    cudaFuncSetAttribute(sim_tf32, cudaFuncAttributeMaxDynamicSharedMemorySize, simSmem);

    dim3 blk(256);
    // Q = x @ Wq            (fp32, precision-critical)
    sgemm_nn<<<dim3(INNER / 128, BATCH * NQ / 128), blk>>>(x, Wq, pQ,
                                                           BATCH * NQ, INNER, DQ);
    // KV = ctx @ Wkv        (fp32, precision-critical)
    sgemm_nn<<<dim3(2 * INNER / 128, BATCH * NK / 128), blk>>>(ctx, Wkv, pKV,
                                                               BATCH * NK, 2 * INNER, DQ);
    // sim = Q @ K^T * scale (4-term TF32 tensor cores)
    sim_tf32<<<dim3(NK / 128, NQ / 128, BATCH * NH), blk, simSmem>>>(pQ, pKV, pS);
    // exact top-64 + softmax + sparse PV (rank-based prefilter)
    topk_attn<<<dim3(BATCH * NH * NQ), dim3(128)>>>(pS, pKV, pO);
    // out = O @ Wout + bout (3xTF32 tensor cores)
    out_tf32<<<dim3(DQ / 128, BATCH * NQ / 128), blk>>>(pO, Wout, bout, out);
}

// round 8
// speedup vs baseline: 1.0760x; 1.0760x over previous
#include <cuda_runtime.h>

#define BATCH 4
#define NQ    2048
#define NK    2048
#define DQ    1024
#define NH    8
#define HD    64
#define INNER 512
#define KKEEP 64

// Scratch (device globals; allocation-free contract)
__device__ float g_Q [BATCH * NQ * INNER];          // 16.8 MB
__device__ float g_KV[BATCH * NK * 2 * INNER];      // 33.5 MB  (K: cols 0..511, V: 512..1023)
__device__ float g_S [134217728];                   // 512 MB   sim [B*H][NQ][NK]
__device__ float g_O [BATCH * NQ * INNER];          // 16.8 MB

// ---- tf32 split helpers + warp MMA --------------------------------------------
__device__ __forceinline__ void split_tf32(float v, unsigned& hi, unsigned& lo) {
    asm("cvt.rna.tf32.f32 %0, %1;" : "=r"(hi) : "f"(v));
    float l = v - __uint_as_float(hi);
    asm("cvt.rna.tf32.f32 %0, %1;" : "=r"(lo) : "f"(l));
}

#define MMA_TF32(c, a, b0, b1) \
    asm("mma.sync.aligned.m16n8k8.row.col.f32.tf32.tf32.f32 " \
        "{%0,%1,%2,%3}, {%4,%5,%6,%7}, {%8,%9}, {%0,%1,%2,%3};" \
        : "+f"((c)[0]), "+f"((c)[1]), "+f"((c)[2]), "+f"((c)[3]) \
        : "r"((a)[0]), "r"((a)[1]), "r"((a)[2]), "r"((a)[3]), "r"(b0), "r"(b1))

// ---------------------------------------------------------------------------
// fp32 SGEMM (NN), double-buffered, ld-parameterized (precision-critical paths).
// 128x128 tile, BK=8, 256 threads, 8x8 microtile.
// ---------------------------------------------------------------------------
__global__ void __launch_bounds__(256) sgemm_nn(
    const float* __restrict__ A, const float* __restrict__ Bm,
    float* __restrict__ C, int M, int N, int K, int lda, int ldb, int ldc)
{
    __shared__ float As[2][8][128];
    __shared__ float Bs[2][8][128];
    const int tid  = threadIdx.x;
    const int row0 = blockIdx.y * 128, col0 = blockIdx.x * 128;
    const int tx   = tid & 15, ty = tid >> 4;
    const int a_row = tid >> 1, a_k = (tid & 1) * 4;
    const int b_k   = tid >> 5, b_col = (tid & 31) * 4;
    const float* Ap = A  + (size_t)(row0 + a_row) * lda + a_k;
    const float* Bp = Bm + (size_t)b_k * ldb + col0 + b_col;

    float acc[8][8];
#pragma unroll
    for (int i = 0; i < 8; i++)
#pragma unroll
        for (int j = 0; j < 8; j++) acc[i][j] = 0.f;

    {
        float4 av = *(const float4*)Ap;
        float4 bv = *(const float4*)Bp;
        As[0][a_k + 0][a_row] = av.x;
        As[0][a_k + 1][a_row] = av.y;
        As[0][a_k + 2][a_row] = av.z;
        As[0][a_k + 3][a_row] = av.w;
        *(float4*)&Bs[0][b_k][b_col] = bv;
    }
    __syncthreads();

    int buf = 0;
    for (int k0 = 8; k0 <= K; k0 += 8) {
        const bool has = (k0 < K);
        float4 av, bv;
        if (has) {
            av = *(const float4*)(Ap + k0);
            bv = *(const float4*)(Bp + (size_t)k0 * ldb);
        }
#pragma unroll
        for (int kk = 0; kk < 8; kk++) {
            float af[8], bf[8];
            *(float4*)&af[0] = *(const float4*)&As[buf][kk][ty * 4];
            *(float4*)&af[4] = *(const float4*)&As[buf][kk][ty * 4 + 64];
            *(float4*)&bf[0] = *(const float4*)&Bs[buf][kk][tx * 4];
            *(float4*)&bf[4] = *(const float4*)&Bs[buf][kk][tx * 4 + 64];
#pragma unroll
            for (int i = 0; i < 8; i++)
#pragma unroll
                for (int j = 0; j < 8; j++)
                    acc[i][j] += af[i] * bf[j];
        }
        if (has) {
            const int nb = buf ^ 1;
            As[nb][a_k + 0][a_row] = av.x;
            As[nb][a_k + 1][a_row] = av.y;
            As[nb][a_k + 2][a_row] = av.z;
            As[nb][a_k + 3][a_row] = av.w;
            *(float4*)&Bs[nb][b_k][b_col] = bv;
            __syncthreads();
            buf = nb;
        }
    }

#pragma unroll
    for (int ih = 0; ih < 2; ih++)
#pragma unroll
        for (int ii = 0; ii < 4; ii++) {
            int row = row0 + ty * 4 + ih * 64 + ii;
            float* Cp = C + (size_t)row * ldc + col0;
#pragma unroll
            for (int jh = 0; jh < 2; jh++) {
                int c = tx * 4 + jh * 64;
                float4 v;
                v.x = acc[ih * 4 + ii][jh * 4 + 0];
                v.y = acc[ih * 4 + ii][jh * 4 + 1];
                v.z = acc[ih * 4 + ii][jh * 4 + 2];
                v.w = acc[ih * 4 + ii][jh * 4 + 3];
                *(float4*)(Cp + c) = v;
            }
        }
}

// ---------------------------------------------------------------------------
// sim via 3-term TF32 tensor-core MMA (NT): S = 0.125 * Q_h . K_h^T
// (identical arithmetic to the passing R6 kernel)
// ---------------------------------------------------------------------------
__global__ void __launch_bounds__(256) sim_tf32(
    const float* __restrict__ Q, const float* __restrict__ KV, float* __restrict__ S)
{
    extern __shared__ float sm[];
    float* Qs = sm;              // [128][68]
    float* Ks = sm + 128 * 68;   // [128][68]
    const int bh = blockIdx.z, b = bh >> 3, h = bh & 7;
    const int i0 = blockIdx.y * 128, j0 = blockIdx.x * 128;
    const int tid = threadIdx.x;

#pragma unroll
    for (int l = 0; l < 8; l++) {
        int idx = tid + l * 256;
        int row = idx >> 4, k0 = (idx & 15) * 4;
        float4 q4 = *(const float4*)(Q  + (size_t)(b * NQ + i0 + row) * INNER       + h * HD + k0);
        *(float4*)(Qs + row * 68 + k0) = q4;
        float4 k4 = *(const float4*)(KV + (size_t)(b * NK + j0 + row) * (2 * INNER) + h * HD + k0);
        *(float4*)(Ks + row * 68 + k0) = k4;
    }
    __syncthreads();

    const int lane = tid & 31, wid = tid >> 5;
    const int wm = (wid & 3) * 32, wn = (wid >> 2) * 64;
    const int gr = lane >> 2, gc = lane & 3;

    float acc[2][8][4];
#pragma unroll
    for (int mi = 0; mi < 2; mi++)
#pragma unroll
        for (int ni = 0; ni < 8; ni++)
#pragma unroll
            for (int q = 0; q < 4; q++) acc[mi][ni][q] = 0.f;

#pragma unroll
    for (int k0 = 0; k0 < 64; k0 += 8) {
        unsigned ahi[2][4], alo[2][4];
#pragma unroll
        for (int mi = 0; mi < 2; mi++) {
            int m = wm + mi * 16 + gr;
            split_tf32(Qs[m * 68 + k0 + gc],           ahi[mi][0], alo[mi][0]);
            split_tf32(Qs[(m + 8) * 68 + k0 + gc],     ahi[mi][1], alo[mi][1]);
            split_tf32(Qs[m * 68 + k0 + 4 + gc],       ahi[mi][2], alo[mi][2]);
            split_tf32(Qs[(m + 8) * 68 + k0 + 4 + gc], ahi[mi][3], alo[mi][3]);
        }
#pragma unroll
        for (int ni = 0; ni < 8; ni++) {
            int n = wn + ni * 8 + gr;
            unsigned bh0, bl0, bh1, bl1;
            split_tf32(Ks[n * 68 + k0 + gc],     bh0, bl0);
            split_tf32(Ks[n * 68 + k0 + 4 + gc], bh1, bl1);
#pragma unroll
            for (int mi = 0; mi < 2; mi++) {
                MMA_TF32(acc[mi][ni], ahi[mi], bh0, bh1);
                MMA_TF32(acc[mi][ni], ahi[mi], bl0, bl1);
                MMA_TF32(acc[mi][ni], alo[mi], bh0, bh1);
            }
        }
    }

    const float scale = 0.125f;
#pragma unroll
    for (int mi = 0; mi < 2; mi++)
#pragma unroll
        for (int ni = 0; ni < 8; ni++) {
            int row = i0 + wm + mi * 16 + gr;
            int col = j0 + wn + ni * 8 + gc * 2;
            float2 v0 = { acc[mi][ni][0] * scale, acc[mi][ni][1] * scale };
            __stcs((float2*)(S + ((size_t)bh * NQ + row) * NK + col), v0);
            float2 v1 = { acc[mi][ni][2] * scale, acc[mi][ni][3] * scale };
            __stcs((float2*)(S + ((size_t)bh * NQ + row + 8) * NK + col), v1);
        }
}

// ---------------------------------------------------------------------------
// Generic 3xTF32 MMA GEMM (NN): C = A @ B (+ bias), ld-parameterized.
// Used for V-half projection (post-selection) and out-projection.
// Block 128x128, BK=8 double-buffered; B transposed into smem at load.
// ---------------------------------------------------------------------------
__global__ void __launch_bounds__(256) gemm_tf32_nn(
    const float* __restrict__ A, const float* __restrict__ Bm,
    const float* __restrict__ bias, float* __restrict__ C,
    int M, int N, int K, int lda, int ldb, int ldc)
{
    __shared__ float As[2][128 * 12];
    __shared__ float Bs[2][128 * 12];
    const int tid  = threadIdx.x;
    const int row0 = blockIdx.y * 128, col0 = blockIdx.x * 128;
    const int a_row = tid >> 1, a_k = (tid & 1) * 4;
    const int b_k   = tid >> 5, b_n = (tid & 31) * 4;
    const float* Ap = A  + (size_t)(row0 + a_row) * lda + a_k;
    const float* Bp = Bm + (size_t)b_k * ldb + col0 + b_n;

    {
        float4 a4 = *(const float4*)Ap;
        *(float4*)(As[0] + a_row * 12 + a_k) = a4;
        float4 b4 = *(const float4*)Bp;
        Bs[0][(b_n + 0) * 12 + b_k] = b4.x;
        Bs[0][(b_n + 1) * 12 + b_k] = b4.y;
        Bs[0][(b_n + 2) * 12 + b_k] = b4.z;
        Bs[0][(b_n + 3) * 12 + b_k] = b4.w;
    }
    __syncthreads();

    const int lane = tid & 31, wid = tid >> 5;
    const int wm = (wid & 3) * 32, wn = (wid >> 2) * 64;
    const int gr = lane >> 2, gc = lane & 3;

    float acc[2][8][4];
#pragma unroll
    for (int mi = 0; mi < 2; mi++)
#pragma unroll
        for (int ni = 0; ni < 8; ni++)
#pragma unroll
            for (int q = 0; q < 4; q++) acc[mi][ni][q] = 0.f;

    int buf = 0;
    for (int k0 = 8; k0 <= K; k0 += 8) {
        const bool has = (k0 < K);
        float4 a4, b4;
        if (has) {
            a4 = *(const float4*)(Ap + k0);
            b4 = *(const float4*)(Bp + (size_t)k0 * ldb);
        }
        unsigned ahi[2][4], alo[2][4];
#pragma unroll
        for (int mi = 0; mi < 2; mi++) {
            int m = wm + mi * 16 + gr;
            split_tf32(As[buf][m * 12 + gc],           ahi[mi][0], alo[mi][0]);
            split_tf32(As[buf][(m + 8) * 12 + gc],     ahi[mi][1], alo[mi][1]);
            split_tf32(As[buf][m * 12 + 4 + gc],       ahi[mi][2], alo[mi][2]);
            split_tf32(As[buf][(m + 8) * 12 + 4 + gc], ahi[mi][3], alo[mi][3]);
        }
#pragma unroll
        for (int ni = 0; ni < 8; ni++) {
            int n = wn + ni * 8 + gr;
            unsigned bh0, bl0, bh1, bl1;
            split_tf32(Bs[buf][n * 12 + gc],     bh0, bl0);
            split_tf32(Bs[buf][n * 12 + 4 + gc], bh1, bl1);
#pragma unroll
            for (int mi = 0; mi < 2; mi++) {
                MMA_TF32(acc[mi][ni], ahi[mi], bh0, bh1);
                MMA_TF32(acc[mi][ni], ahi[mi], bl0, bl1);
                MMA_TF32(acc[mi][ni], alo[mi], bh0, bh1);
            }
        }
        if (has) {
            const int nb = buf ^ 1;
            *(float4*)(As[nb] + a_row * 12 + a_k) = a4;
            Bs[nb][(b_n + 0) * 12 + b_k] = b4.x;
            Bs[nb][(b_n + 1) * 12 + b_k] = b4.y;
            Bs[nb][(b_n + 2) * 12 + b_k] = b4.z;
            Bs[nb][(b_n + 3) * 12 + b_k] = b4.w;
            __syncthreads();
            buf = nb;
        }
    }

#pragma unroll
    for (int mi = 0; mi < 2; mi++)
#pragma unroll
        for (int ni = 0; ni < 8; ni++) {
            int row = row0 + wm + mi * 16 + gr;
            int col = col0 + wn + ni * 8 + gc * 2;
            float bx = 0.f, by = 0.f;
            if (bias) { bx = bias[col]; by = bias[col + 1]; }
            float2 v0 = { acc[mi][ni][0] + bx, acc[mi][ni][1] + by };
            *(float2*)(C + (size_t)row * ldc + col) = v0;
            float2 v1 = { acc[mi][ni][2] + bx, acc[mi][ni][3] + by };
            *(float2*)(C + (size_t)(row + 8) * ldc + col) = v1;
        }
}

// ---------------------------------------------------------------------------
// Per query row: exact top-64.
//  Threshold: per-warp shuffle-bitonic sort of 32 thread-maxes (desc);
//  t_hat = min over warps of warp's 16th-largest. Validity: each warp has >=16
//  threads with max >= t_hat, each contributing >=1 value => >=64 values >=
//  t_hat => all true top-64 >= t_hat (exact prefilter).
//  Then compact candidates, exact rank-select on composite keys (value desc,
//  index asc == jax.lax.top_k ties), softmax, sparse PV.
// ---------------------------------------------------------------------------
__device__ __forceinline__ unsigned fkey(float f) {
    unsigned u = __float_as_uint(f);
    return (u & 0x80000000u) ? ~u : (u | 0x80000000u);
}
__device__ __forceinline__ float unfkey(unsigned k) {
    unsigned u = (k & 0x80000000u) ? (k & 0x7fffffffu) : ~k;
    return __uint_as_float(u);
}

__global__ void __launch_bounds__(128, 12) topk_attn(
    const float* __restrict__ S, const float* __restrict__ KV, float* __restrict__ O)
{
    const int r  = blockIdx.x;
    const int bh = r >> 11, i = r & 2047;
    const int b  = bh >> 3, h = bh & 7;
    const float* srow = S + (size_t)r * NK;

    __shared__ __align__(16) unsigned long long ckey[2049];  // worst-case + pad
    __shared__ float warpthr[4];
    __shared__ float selv[64];
    __shared__ int   seli[64];
    __shared__ float s_wsum;
    __shared__ int   s_ncand;
    __shared__ float w[64];
    __shared__ float part[64];

    const int tid = threadIdx.x;
    const int lane = tid & 31, wrp = tid >> 5;
    if (tid == 0) s_ncand = 0;

    float vals[16];
#pragma unroll
    for (int t = 0; t < 4; t++) {
        float4 v = __ldcs((const float4*)srow + tid + t * 128);
        vals[t * 4 + 0] = v.x; vals[t * 4 + 1] = v.y;
        vals[t * 4 + 2] = v.z; vals[t * 4 + 3] = v.w;
    }
    float tmax = vals[0];
#pragma unroll
    for (int t = 1; t < 16; t++) tmax = fmaxf(tmax, vals[t]);

    // warp bitonic sort (descending; max at lane 0) of the 32 thread-maxes
    {
        float v = tmax;
#pragma unroll
        for (int k = 2; k <= 32; k <<= 1) {
#pragma unroll
            for (int j = k >> 1; j > 0; j >>= 1) {
                float o = __shfl_xor_sync(0xffffffffu, v, j);
                bool ascBlock = ((lane & k) != 0);
                bool upper    = ((lane & j) != 0);
                v = (upper == ascBlock) ? fmaxf(v, o) : fminf(v, o);
            }
        }
        float t_w = __shfl_sync(0xffffffffu, v, 15);   // 16th largest in warp
        if (lane == 0) warpthr[wrp] = t_w;
    }
    __syncthreads();
    const float thr = fminf(fminf(warpthr[0], warpthr[1]),
                            fminf(warpthr[2], warpthr[3]));

    // warp-aggregated compaction of candidates (v >= thr)
#pragma unroll
    for (int t = 0; t < 16; t++) {
        bool p = (vals[t] >= thr);
        unsigned ball = __ballot_sync(0xffffffffu, p);
        if (ball) {
            int base;
            if (lane == 0) base = atomicAdd(&s_ncand, __popc(ball));
            base = __shfl_sync(0xffffffffu, base, 0);
            if (p) {
                int off = __popc(ball & ((1u << lane) - 1u));
                int j = (tid + (t >> 2) * 128) * 4 + (t & 3);
                ckey[base + off] =
                    ((unsigned long long)fkey(vals[t]) << 32) | (unsigned)(2047 - j);
            }
        }
    }
    __syncthreads();
    const int nc = s_ncand;
    if (tid == 0) ckey[nc] = 0ull;    // pad so paired reads are safe
    __syncthreads();

    // exact top-64 by rank over candidates (vectorized smem reads);
    // keys unique (index embedded) -> ranks unique; write at final position
    for (int c = tid; c < nc; c += 128) {
        unsigned long long k = ckey[c];
        int rk = 0;
        for (int o = 0; o < nc; o += 2) {
            ulonglong2 kk = *(const ulonglong2*)&ckey[o];
            rk += (kk.x > k) + (kk.y > k);
        }
        if (rk < KKEEP) {
            selv[rk] = unfkey((unsigned)(k >> 32));
            seli[rk] = 2047 - (int)(k & 0xffffffffu);
        }
    }
    __syncthreads();   // selv[0] = row max

    if (tid < 64) w[tid] = expf(selv[tid] - selv[0]);
    __syncthreads();
    if (tid < 32) {
        float s = w[tid] + w[tid + 32];
#pragma unroll
        for (int off = 16; off; off >>= 1)
            s += __shfl_xor_sync(0xffffffffu, s, off);
        if (tid == 0) s_wsum = s;
    }
    __syncthreads();

    const int g = tid >> 6, d = tid & 63;
    const float* Vbase = KV + (size_t)b * NK * (2 * INNER) + INNER + h * HD + d;
    float acc = 0.f;
#pragma unroll 4
    for (int jj = 0; jj < 32; jj++) {
        int j = g * 32 + jj;
        acc += w[j] * Vbase[(size_t)seli[j] * (2 * INNER)];
    }
    if (g == 1) part[d] = acc;
    __syncthreads();
    if (g == 0) {
        float o = (acc + part[d]) / s_wsum;
        O[((size_t)(b * NQ + i)) * INNER + h * HD + d] = o;
    }
}

// ---------------------------------------------------------------------------
extern "C" void kernel_launch(void* const* d_in, const int* in_sizes, int n_in,
                              void* d_out, int out_size)
{
    const float* x    = (const float*)d_in[0];
    const float* ctx  = (const float*)d_in[1];
    const float* Wq   = (const float*)d_in[2];
    const float* Wkv  = (const float*)d_in[3];
    const float* Wout = (const float*)d_in[4];
    const float* bout = (const float*)d_in[5];
    float* out = (float*)d_out;

    float *pQ, *pKV, *pS, *pO;
    cudaGetSymbolAddress((void**)&pQ,  g_Q);
    cudaGetSymbolAddress((void**)&pKV, g_KV);
    cudaGetSymbolAddress((void**)&pS,  g_S);
    cudaGetSymbolAddress((void**)&pO,  g_O);

    const int simSmem = 2 * 128 * 68 * sizeof(float);   // 69632 B
    cudaFuncSetAttribute(sim_tf32, cudaFuncAttributeMaxDynamicSharedMemorySize, simSmem);

    dim3 blk(256);
    // Q = x @ Wq   (fp32; feeds selection)
    sgemm_nn<<<dim3(INNER / 128, BATCH * NQ / 128), blk>>>(
        x, Wq, pQ, BATCH * NQ, INNER, DQ, DQ, INNER, INNER);
    // K-half: ctx @ Wkv[:, 0:512]  (fp32; feeds selection)
    sgemm_nn<<<dim3(INNER / 128, BATCH * NK / 128), blk>>>(
        ctx, Wkv, pKV, BATCH * NK, INNER, DQ, DQ, 2 * INNER, 2 * INNER);
    // V-half: ctx @ Wkv[:, 512:1024]  (3xTF32; post-selection, safe)
    gemm_tf32_nn<<<dim3(INNER / 128, BATCH * NK / 128), blk>>>(
        ctx, Wkv + INNER, nullptr, pKV + INNER,
        BATCH * NK, INNER, DQ, DQ, 2 * INNER, 2 * INNER);
    // sim = Q @ K^T * scale (3-term TF32, identical to R6)
    sim_tf32<<<dim3(NK / 128, NQ / 128, BATCH * NH), blk, simSmem>>>(pQ, pKV, pS);
    // exact top-64 + softmax + sparse PV
    topk_attn<<<dim3(BATCH * NH * NQ), dim3(128)>>>(pS, pKV, pO);
    // out = O @ Wout + bout (3xTF32)
    gemm_tf32_nn<<<dim3(DQ / 128, BATCH * NQ / 128), blk>>>(
        pO, Wout, bout, out, BATCH * NQ, DQ, INNER, INNER, DQ, DQ);
}